// round 2
// baseline (speedup 1.0000x reference)
#include <cuda_runtime.h>
#include <cuda_fp16.h>
#include <mma.h>

using namespace nvcuda;

#define D_FEAT  128
#define HIDDEN  256
#define NOUT    512      // 2*HIDDEN (A and B halves)
#define MAX_NODES 100000

// Scratch: per-node precomputed A' = W1a*h + b1 (fp16) and B = W1b*h (fp16)
__device__ __half g_A[(size_t)MAX_NODES * HIDDEN];   // 51.2 MB
__device__ __half g_B[(size_t)MAX_NODES * HIDDEN];   // 51.2 MB
__device__ __half g_W[D_FEAT * NOUT];                // Wcat[k][j], 128 KB

// ---------------------------------------------------------------------------
// Prep: Wcat[k][j] = W1_w[j][k] (j<256)  |  W1_w[j-256][128+k] (j>=256)
// W1_w is [256, 256] row-major (torch layout [out, in])
// ---------------------------------------------------------------------------
__global__ void prep_w_kernel(const float* __restrict__ W1) {
    int idx = blockIdx.x * blockDim.x + threadIdx.x;
    if (idx >= D_FEAT * NOUT) return;
    int k = idx / NOUT;
    int j = idx % NOUT;
    float v = (j < HIDDEN) ? W1[(size_t)j * (2 * D_FEAT) + k]
                           : W1[(size_t)(j - HIDDEN) * (2 * D_FEAT) + D_FEAT + k];
    g_W[(size_t)k * NOUT + j] = __float2half(v);
}

// ---------------------------------------------------------------------------
// Precompute GEMM: C[100000, 512] = h[100000,128] @ Wcat[128,512]
// fp16 inputs, fp32 accumulate (wmma / HMMA). Epilogue folds b1 into A half.
// Block: 256 threads (8 warps). Tile: M=128, N=64, K=128 (full K in smem).
// ---------------------------------------------------------------------------
#define MT 128
#define NT 64
#define SA_LD (D_FEAT + 8)   // 136, multiple of 8

__global__ void __launch_bounds__(256) gemm_ab_kernel(
    const float* __restrict__ h, const float* __restrict__ b1, int n_nodes)
{
    __shared__ __half sA[MT * SA_LD];   // 128*136*2 = 34816 B

    int mBase = blockIdx.x * MT;
    int nBase = blockIdx.y * NT;

    // Load A tile (fp32 -> fp16) into smem, zero-fill OOB rows.
    for (int i = threadIdx.x; i < MT * (D_FEAT / 4); i += 256) {
        int r  = i / (D_FEAT / 4);
        int c4 = i % (D_FEAT / 4);
        float4 v = make_float4(0.f, 0.f, 0.f, 0.f);
        int row = mBase + r;
        if (row < n_nodes) v = *(const float4*)(h + (size_t)row * D_FEAT + c4 * 4);
        __half* p = &sA[r * SA_LD + c4 * 4];
        p[0] = __float2half(v.x);
        p[1] = __float2half(v.y);
        p[2] = __float2half(v.z);
        p[3] = __float2half(v.w);
    }
    __syncthreads();

    int wid = threadIdx.x >> 5;

    wmma::fragment<wmma::accumulator, 16, 16, 16, float> acc[4];
#pragma unroll
    for (int f = 0; f < 4; f++) wmma::fill_fragment(acc[f], 0.0f);

#pragma unroll
    for (int k = 0; k < D_FEAT; k += 16) {
        wmma::fragment<wmma::matrix_a, 16, 16, 16, __half, wmma::row_major> fa;
        wmma::load_matrix_sync(fa, &sA[(wid * 16) * SA_LD + k], SA_LD);
#pragma unroll
        for (int f = 0; f < 4; f++) {
            wmma::fragment<wmma::matrix_b, 16, 16, 16, __half, wmma::row_major> fb;
            // Wcat is tiny (128 KB) -> L2/L1 resident, load fragments directly.
            wmma::load_matrix_sync(fb, g_W + (size_t)k * NOUT + nBase + f * 16, NOUT);
            wmma::mma_sync(acc[f], fa, fb, acc[f]);
        }
    }

    // Epilogue: reuse sA as fp32 staging (needs 128*64*4 = 32 KB <= 34.8 KB).
    __syncthreads();
    float* sC = reinterpret_cast<float*>(sA);
#pragma unroll
    for (int f = 0; f < 4; f++)
        wmma::store_matrix_sync(sC + wid * (16 * NT) + f * 16, acc[f], NT,
                                wmma::mem_row_major);
    __syncthreads();

    for (int i = threadIdx.x; i < MT * NT; i += 256) {
        int r = i >> 6;       // 0..127
        int c = i & 63;       // 0..63
        int row = mBase + r;
        if (row >= n_nodes) continue;
        float v = sC[(r >> 4) * (16 * NT) + (r & 15) * NT + c];
        int j = nBase + c;
        if (j < HIDDEN) {
            v += b1[j];  // fold bias into A'
            g_A[(size_t)row * HIDDEN + j] = __float2half(v);
        } else {
            g_B[(size_t)row * HIDDEN + (j - HIDDEN)] = __float2half(v);
        }
    }
}

// ---------------------------------------------------------------------------
// Edge kernel: one warp per edge.
//   z = A'[src] + B[dst];  score = W2 . relu(z) + b2
// Each lane owns 8 contiguous hidden dims: 1 LDG.128 per operand per lane.
// NOTE: indices are int32 (JAX silently downcasts int64 without x64 mode).
// ---------------------------------------------------------------------------
__global__ void __launch_bounds__(256) edge_kernel(
    const int* __restrict__ src, const int* __restrict__ dst,
    const float* __restrict__ W2, const float* __restrict__ b2,
    float* __restrict__ out, int E)
{
    __shared__ float sW[HIDDEN];
    __shared__ float sb2;
    for (int i = threadIdx.x; i < HIDDEN; i += 256) sW[i] = W2[i];
    if (threadIdx.x == 0) sb2 = b2[0];
    __syncthreads();

    int lane = threadIdx.x & 31;
    int e = blockIdx.x * 8 + (threadIdx.x >> 5);
    if (e >= E) return;

    float w[8];
#pragma unroll
    for (int i = 0; i < 8; i++) w[i] = sW[lane * 8 + i];

    int s = src[e];
    int d = dst[e];

    uint4 va = *(const uint4*)(g_A + (size_t)s * HIDDEN + lane * 8);
    uint4 vb = *(const uint4*)(g_B + (size_t)d * HIDDEN + lane * 8);

    const __half2* pa = reinterpret_cast<const __half2*>(&va);
    const __half2* pb = reinterpret_cast<const __half2*>(&vb);
    const __half2 zero2 = __float2half2_rn(0.f);

    float acc = 0.f;
#pragma unroll
    for (int i = 0; i < 4; i++) {
        __half2 z2 = __hmax2(__hadd2(pa[i], pb[i]), zero2);   // relu(A'+B)
        float2 f = __half22float2(z2);
        acc = fmaf(f.x, w[2 * i + 0], acc);
        acc = fmaf(f.y, w[2 * i + 1], acc);
    }

    // warp reduce
#pragma unroll
    for (int off = 16; off > 0; off >>= 1)
        acc += __shfl_xor_sync(0xFFFFFFFFu, acc, off);

    if (lane == 0) out[e] = acc + sb2;
}

// ---------------------------------------------------------------------------
extern "C" void kernel_launch(void* const* d_in, const int* in_sizes, int n_in,
                              void* d_out, int out_size)
{
    const float* h    = (const float*)d_in[0];
    const int*   src  = (const int*)d_in[1];
    const int*   dst  = (const int*)d_in[2];
    const float* W1_w = (const float*)d_in[3];
    const float* W1_b = (const float*)d_in[4];
    const float* W2_w = (const float*)d_in[5];
    const float* W2_b = (const float*)d_in[6];
    float* out = (float*)d_out;

    int n_nodes = in_sizes[0] / D_FEAT;
    int E = in_sizes[1];

    // 1) Reorder + convert W1 -> Wcat fp16
    prep_w_kernel<<<(D_FEAT * NOUT + 255) / 256, 256>>>(W1_w);

    // 2) Precompute A' (with b1) and B per node (fp16, fp32-accum GEMM)
    dim3 ggrid((n_nodes + MT - 1) / MT, NOUT / NT);
    gemm_ab_kernel<<<ggrid, 256>>>(h, W1_b, n_nodes);

    // 3) Per-edge: gather, add, relu, dot
    edge_kernel<<<(E + 7) / 8, 256>>>(src, dst, W2_w, W2_b, out, E);
}

// round 4
// speedup vs baseline: 1.0021x; 1.0021x over previous
#include <cuda_runtime.h>
#include <cuda_fp16.h>
#include <mma.h>

using namespace nvcuda;

#define D_FEAT  128
#define HIDDEN  256
#define NOUT    512      // 2*HIDDEN (A and B halves)
#define MAX_NODES 100000

// Scratch: per-node precomputed A' = W1a*h + b1 (fp16) and B = W1b*h (fp16)
__device__ __half g_A[(size_t)MAX_NODES * HIDDEN];   // 51.2 MB
__device__ __half g_B[(size_t)MAX_NODES * HIDDEN];   // 51.2 MB
__device__ __half g_W[D_FEAT * NOUT];                // Wcat[k][j], 128 KB
__device__ __half g_h16[(size_t)MAX_NODES * D_FEAT]; // 25.6 MB

// ---------------------------------------------------------------------------
// Prep: Wcat[k][j] = W1_w[j][k] (j<256) | W1_w[j-256][128+k] (j>=256)
// ---------------------------------------------------------------------------
__global__ void prep_w_kernel(const float* __restrict__ W1) {
    int idx = blockIdx.x * blockDim.x + threadIdx.x;
    if (idx >= D_FEAT * NOUT) return;
    int k = idx / NOUT;
    int j = idx % NOUT;
    float v = (j < HIDDEN) ? W1[(size_t)j * (2 * D_FEAT) + k]
                           : W1[(size_t)(j - HIDDEN) * (2 * D_FEAT) + D_FEAT + k];
    g_W[(size_t)k * NOUT + j] = __float2half(v);
}

// ---------------------------------------------------------------------------
// Convert h (fp32) -> g_h16 (fp16), vectorized: 4 floats in, 8B out per thread
// ---------------------------------------------------------------------------
__global__ void convert_h_kernel(const float* __restrict__ h, int n_elem4) {
    int i = blockIdx.x * blockDim.x + threadIdx.x;
    if (i >= n_elem4) return;
    float4 v = ((const float4*)h)[i];
    __half2 lo = __floats2half2_rn(v.x, v.y);
    __half2 hi = __floats2half2_rn(v.z, v.w);
    ((__half2*)g_h16)[2 * i]     = lo;
    ((__half2*)g_h16)[2 * i + 1] = hi;
}

// ---------------------------------------------------------------------------
// Precompute GEMM: C[n,512] = h16[n,128] @ Wcat[128,512], fp32 accumulate.
// Block: 256 threads (8 warps). Tile: M=128, N=128 (grid.y = 4), K=128.
// grid.y 0,1 -> g_A (bias folded); grid.y 2,3 -> g_B.
// ---------------------------------------------------------------------------
#define MT 128
#define NT 128
#define SA_LD (D_FEAT + 8)   // 136 halves; row stride 272B (16B-multiple)

__global__ void __launch_bounds__(256) gemm_ab_kernel(
    const float* __restrict__ b1, int n_nodes)
{
    __shared__ __half sA[MT * SA_LD];   // 34816 B

    int mBase = blockIdx.x * MT;
    int nBase = blockIdx.y * NT;

    // Load h16 tile into smem: 128 rows x 128 halves, 16B per thread-iter.
    for (int i = threadIdx.x; i < MT * (D_FEAT / 8); i += 256) {
        int r  = i >> 4;           // /16 groups of 8
        int c8 = i & 15;
        uint4 v = make_uint4(0, 0, 0, 0);
        int row = mBase + r;
        if (row < n_nodes)
            v = *(const uint4*)(g_h16 + (size_t)row * D_FEAT + c8 * 8);
        *(uint4*)(&sA[r * SA_LD + c8 * 8]) = v;
    }
    __syncthreads();

    int wid = threadIdx.x >> 5;

    wmma::fragment<wmma::accumulator, 16, 16, 16, float> acc[8];
#pragma unroll
    for (int f = 0; f < 8; f++) wmma::fill_fragment(acc[f], 0.0f);

#pragma unroll
    for (int k = 0; k < D_FEAT; k += 16) {
        wmma::fragment<wmma::matrix_a, 16, 16, 16, __half, wmma::row_major> fa;
        wmma::load_matrix_sync(fa, &sA[(wid * 16) * SA_LD + k], SA_LD);
#pragma unroll
        for (int f = 0; f < 8; f++) {
            wmma::fragment<wmma::matrix_b, 16, 16, 16, __half, wmma::row_major> fb;
            wmma::load_matrix_sync(fb, g_W + (size_t)k * NOUT + nBase + f * 16, NOUT);
            wmma::mma_sync(acc[f], fa, fb, acc[f]);
        }
    }

    // Epilogue in two N-halves of 64 cols, staged through smem (reuses sA).
    bool isA = (nBase < HIDDEN);
    __half* gOut = isA ? g_A : g_B;
    int jBase = isA ? nBase : (nBase - HIDDEN);

#pragma unroll
    for (int nh = 0; nh < 2; nh++) {
        __syncthreads();
        float* sC = reinterpret_cast<float*>(sA);   // 128 x 64 fp32 = 32 KB
#pragma unroll
        for (int f = 0; f < 4; f++)
            wmma::store_matrix_sync(sC + wid * (16 * 64) + f * 16,
                                    acc[nh * 4 + f], 64, wmma::mem_row_major);
        __syncthreads();

        // 1024 items: (row, 8-col group). 4 iters of 256 threads.
        for (int i = threadIdx.x; i < MT * 8; i += 256) {
            int r = i >> 3;
            int g = i & 7;
            int row = mBase + r;
            if (row >= n_nodes) continue;
            int j = jBase + nh * 64 + g * 8;
            const float* p = sC + (r >> 4) * (16 * 64) + (r & 15) * 64 + g * 8;
            float v0 = p[0], v1 = p[1], v2 = p[2], v3 = p[3];
            float v4 = p[4], v5 = p[5], v6 = p[6], v7 = p[7];
            if (isA) {
                float4 ba = *(const float4*)(b1 + j);
                float4 bb = *(const float4*)(b1 + j + 4);
                v0 += ba.x; v1 += ba.y; v2 += ba.z; v3 += ba.w;
                v4 += bb.x; v5 += bb.y; v6 += bb.z; v7 += bb.w;
            }
            __half2 h0 = __floats2half2_rn(v0, v1);
            __half2 h1 = __floats2half2_rn(v2, v3);
            __half2 h2 = __floats2half2_rn(v4, v5);
            __half2 h3 = __floats2half2_rn(v6, v7);
            uint4 pk;
            pk.x = *(const unsigned*)&h0; pk.y = *(const unsigned*)&h1;
            pk.z = *(const unsigned*)&h2; pk.w = *(const unsigned*)&h3;
            *(uint4*)(gOut + (size_t)row * HIDDEN + j) = pk;
        }
    }
}

// ---------------------------------------------------------------------------
// Edge kernel: 2 edges per warp, 16 lanes per edge, 16 dims per lane.
//   z = A'[src] + B[dst];  score = W2 . relu(z) + b2
// ---------------------------------------------------------------------------
__global__ void __launch_bounds__(256) edge_kernel(
    const int* __restrict__ src, const int* __restrict__ dst,
    const float* __restrict__ W2, const float* __restrict__ b2,
    float* __restrict__ out, int E)
{
    __shared__ float sW[HIDDEN];
    __shared__ float sb2;
    for (int i = threadIdx.x; i < HIDDEN; i += 256) sW[i] = W2[i];
    if (threadIdx.x == 0) sb2 = b2[0];
    __syncthreads();

    int lane = threadIdx.x & 31;
    int sub  = lane & 15;            // lane within edge-group
    int e = blockIdx.x * 16 + (threadIdx.x >> 5) * 2 + (lane >> 4);

    float w[16];
#pragma unroll
    for (int i = 0; i < 16; i++) w[i] = sW[sub * 16 + i];

    float acc = 0.f;
    if (e < E) {
        int s = src[e];
        int d = dst[e];
        const __half* pA = g_A + (size_t)s * HIDDEN + sub * 16;
        const __half* pB = g_B + (size_t)d * HIDDEN + sub * 16;

        uint4 va0 = *(const uint4*)(pA);
        uint4 va1 = *(const uint4*)(pA + 8);
        uint4 vb0 = *(const uint4*)(pB);
        uint4 vb1 = *(const uint4*)(pB + 8);

        const __half2* pa0 = (const __half2*)&va0;
        const __half2* pa1 = (const __half2*)&va1;
        const __half2* pb0 = (const __half2*)&vb0;
        const __half2* pb1 = (const __half2*)&vb1;
        const __half2 zero2 = __float2half2_rn(0.f);

#pragma unroll
        for (int i = 0; i < 4; i++) {
            __half2 z2 = __hmax2(__hadd2(pa0[i], pb0[i]), zero2);
            float2 f = __half22float2(z2);
            acc = fmaf(f.x, w[2 * i + 0], acc);
            acc = fmaf(f.y, w[2 * i + 1], acc);
        }
#pragma unroll
        for (int i = 0; i < 4; i++) {
            __half2 z2 = __hmax2(__hadd2(pa1[i], pb1[i]), zero2);
            float2 f = __half22float2(z2);
            acc = fmaf(f.x, w[8 + 2 * i + 0], acc);
            acc = fmaf(f.y, w[8 + 2 * i + 1], acc);
        }
    }

    // reduce within each 16-lane group
#pragma unroll
    for (int off = 8; off > 0; off >>= 1)
        acc += __shfl_xor_sync(0xFFFFFFFFu, acc, off);

    if (sub == 0 && e < E) out[e] = acc + sb2;
}

// ---------------------------------------------------------------------------
extern "C" void kernel_launch(void* const* d_in, const int* in_sizes, int n_in,
                              void* d_out, int out_size)
{
    const float* h    = (const float*)d_in[0];
    const int*   src  = (const int*)d_in[1];
    const int*   dst  = (const int*)d_in[2];
    const float* W1_w = (const float*)d_in[3];
    const float* W1_b = (const float*)d_in[4];
    const float* W2_w = (const float*)d_in[5];
    const float* W2_b = (const float*)d_in[6];
    float* out = (float*)d_out;

    int n_nodes = in_sizes[0] / D_FEAT;
    int E = in_sizes[1];

    // 1) Weight reorder + h fp16 conversion
    prep_w_kernel<<<(D_FEAT * NOUT + 255) / 256, 256>>>(W1_w);
    int n4 = in_sizes[0] / 4;
    convert_h_kernel<<<(n4 + 255) / 256, 256>>>(h, n4);

    // 2) Precompute A' (with b1) and B per node
    dim3 ggrid((n_nodes + MT - 1) / MT, NOUT / NT);
    gemm_ab_kernel<<<ggrid, 256>>>(W1_b, n_nodes);

    // 3) Per-edge: gather, add, relu, dot
    edge_kernel<<<(E + 15) / 16, 256>>>(src, dst, W2_w, W2_b, out, E);
}

// round 5
// speedup vs baseline: 1.3937x; 1.3907x over previous
#include <cuda_runtime.h>
#include <cuda_fp16.h>
#include <mma.h>

using namespace nvcuda;

#define D_FEAT  128
#define HIDDEN  256
#define NOUT    512      // 2*HIDDEN (A and B halves)
#define MAX_NODES 100000

// Scratch: per-node precomputed A' = W1a*h + b1 (fp16) and B = W1b*h (fp16)
__device__ __half g_A[(size_t)MAX_NODES * HIDDEN];   // 51.2 MB
__device__ __half g_B[(size_t)MAX_NODES * HIDDEN];   // 51.2 MB
__device__ __half g_W[D_FEAT * NOUT];                // Wcat[k][j], 128 KB

// ---------------------------------------------------------------------------
// Prep: Wcat[k][j] = W1_w[j][k] (j<256) | W1_w[j-256][128+k] (j>=256)
// ---------------------------------------------------------------------------
__global__ void prep_w_kernel(const float* __restrict__ W1) {
    int idx = blockIdx.x * blockDim.x + threadIdx.x;
    if (idx >= D_FEAT * NOUT) return;
    int k = idx / NOUT;
    int j = idx % NOUT;
    float v = (j < HIDDEN) ? W1[(size_t)j * (2 * D_FEAT) + k]
                           : W1[(size_t)(j - HIDDEN) * (2 * D_FEAT) + D_FEAT + k];
    g_W[(size_t)k * NOUT + j] = __float2half(v);
}

// ---------------------------------------------------------------------------
// Precompute GEMM: C[n,512] = h[n,128] @ Wcat[128,512], fp32 accumulate.
// One block = 128 rows; loops over 4 N-slices of 128 cols with W staged in
// smem. h loaded once (fp32->fp16 inline). Dynamic smem: 68 KB.
//   sA: 128 x 136 halves (34816 B)   [rows tile, persistent across slices]
//   sW: 128 x 136 halves (34816 B)   [W slice; reused as fp32 sC staging]
// ---------------------------------------------------------------------------
#define MT 128
#define SLD 136            // padded leading dim (halves)

__global__ void __launch_bounds__(256) gemm_ab_kernel(
    const float* __restrict__ h, const float* __restrict__ b1, int n_nodes)
{
    extern __shared__ char dsm[];
    __half* sA = reinterpret_cast<__half*>(dsm);
    __half* sW = reinterpret_cast<__half*>(dsm + MT * SLD * 2);

    int mBase = blockIdx.x * MT;
    int wid = threadIdx.x >> 5;

    // Load h tile (fp32 -> fp16): 128 rows x 32 float4 = 4096 items.
    for (int i = threadIdx.x; i < MT * (D_FEAT / 4); i += 256) {
        int r  = i >> 5;
        int c4 = i & 31;
        float4 v = make_float4(0.f, 0.f, 0.f, 0.f);
        int row = mBase + r;
        if (row < n_nodes) v = *(const float4*)(h + (size_t)row * D_FEAT + c4 * 4);
        __half2 lo = __floats2half2_rn(v.x, v.y);
        __half2 hi = __floats2half2_rn(v.z, v.w);
        uint2 pk;
        pk.x = *(const unsigned*)&lo;
        pk.y = *(const unsigned*)&hi;
        *(uint2*)(&sA[r * SLD + c4 * 4]) = pk;
    }

    for (int ns = 0; ns < 4; ns++) {
        int nBase = ns * MT;
        __syncthreads();   // prior epilogue reads of sW-region done; sA ready (ns=0)

        // Stage W slice: 128 k-rows x 128 cols, 8 halves per item.
        for (int i = threadIdx.x; i < MT * (MT / 8); i += 256) {
            int k  = i >> 4;
            int c8 = i & 15;
            *(uint4*)(&sW[k * SLD + c8 * 8]) =
                *(const uint4*)(g_W + (size_t)k * NOUT + nBase + c8 * 8);
        }
        __syncthreads();

        wmma::fragment<wmma::accumulator, 16, 16, 16, float> acc[8];
#pragma unroll
        for (int f = 0; f < 8; f++) wmma::fill_fragment(acc[f], 0.0f);

#pragma unroll
        for (int k = 0; k < D_FEAT; k += 16) {
            wmma::fragment<wmma::matrix_a, 16, 16, 16, __half, wmma::row_major> fa;
            wmma::load_matrix_sync(fa, &sA[(wid * 16) * SLD + k], SLD);
#pragma unroll
            for (int f = 0; f < 8; f++) {
                wmma::fragment<wmma::matrix_b, 16, 16, 16, __half, wmma::row_major> fb;
                wmma::load_matrix_sync(fb, &sW[k * SLD + f * 16], SLD);
                wmma::mma_sync(acc[f], fa, fb, acc[f]);
            }
        }

        bool isA = (nBase < HIDDEN);
        __half* gOut = isA ? g_A : g_B;
        int jBase = isA ? nBase : (nBase - HIDDEN);

        // Epilogue in two 64-col halves staged through sW region (32 KB fp32).
        float* sC = reinterpret_cast<float*>(sW);
#pragma unroll
        for (int nh = 0; nh < 2; nh++) {
            __syncthreads();   // all warps done reading sW (nh=0) / sC reads (nh=1)
#pragma unroll
            for (int f = 0; f < 4; f++)
                wmma::store_matrix_sync(sC + wid * (16 * 64) + f * 16,
                                        acc[nh * 4 + f], 64, wmma::mem_row_major);
            __syncthreads();

            for (int i = threadIdx.x; i < MT * 8; i += 256) {
                int r = i >> 3;
                int g = i & 7;
                int row = mBase + r;
                if (row >= n_nodes) continue;
                int j = jBase + nh * 64 + g * 8;
                const float* p = sC + (r >> 4) * (16 * 64) + (r & 15) * 64 + g * 8;
                float v0 = p[0], v1 = p[1], v2 = p[2], v3 = p[3];
                float v4 = p[4], v5 = p[5], v6 = p[6], v7 = p[7];
                if (isA) {
                    float4 ba = *(const float4*)(b1 + j);
                    float4 bb = *(const float4*)(b1 + j + 4);
                    v0 += ba.x; v1 += ba.y; v2 += ba.z; v3 += ba.w;
                    v4 += bb.x; v5 += bb.y; v6 += bb.z; v7 += bb.w;
                }
                __half2 h0 = __floats2half2_rn(v0, v1);
                __half2 h1 = __floats2half2_rn(v2, v3);
                __half2 h2 = __floats2half2_rn(v4, v5);
                __half2 h3 = __floats2half2_rn(v6, v7);
                uint4 pk;
                pk.x = *(const unsigned*)&h0; pk.y = *(const unsigned*)&h1;
                pk.z = *(const unsigned*)&h2; pk.w = *(const unsigned*)&h3;
                *(uint4*)(gOut + (size_t)row * HIDDEN + j) = pk;
            }
        }
    }
}

// ---------------------------------------------------------------------------
// Edge kernel: 2 edges per warp, 16 lanes per edge, 16 dims per lane.
// Table gathers use ld.global.cg (L2-only, no L1 allocate: rows have no
// intra-SM reuse; keeps the L1tex fill path out of the way).
// ---------------------------------------------------------------------------
__device__ __forceinline__ uint4 ldg_cg_128(const void* p) {
    uint4 v;
    asm("ld.global.cg.v4.u32 {%0,%1,%2,%3}, [%4];"
        : "=r"(v.x), "=r"(v.y), "=r"(v.z), "=r"(v.w) : "l"(p));
    return v;
}

__global__ void __launch_bounds__(256) edge_kernel(
    const int* __restrict__ src, const int* __restrict__ dst,
    const float* __restrict__ W2, const float* __restrict__ b2,
    float* __restrict__ out, int E)
{
    __shared__ float sW[HIDDEN];
    __shared__ float sb2;
    for (int i = threadIdx.x; i < HIDDEN; i += 256) sW[i] = W2[i];
    if (threadIdx.x == 0) sb2 = b2[0];
    __syncthreads();

    int lane = threadIdx.x & 31;
    int sub  = lane & 15;            // lane within edge-group
    int e = blockIdx.x * 16 + (threadIdx.x >> 5) * 2 + (lane >> 4);

    float w[16];
#pragma unroll
    for (int i = 0; i < 16; i++) w[i] = sW[sub * 16 + i];

    float acc = 0.f;
    if (e < E) {
        int s = src[e];
        int d = dst[e];
        const __half* pA = g_A + (size_t)s * HIDDEN + sub * 16;
        const __half* pB = g_B + (size_t)d * HIDDEN + sub * 16;

        uint4 va0 = ldg_cg_128(pA);
        uint4 va1 = ldg_cg_128(pA + 8);
        uint4 vb0 = ldg_cg_128(pB);
        uint4 vb1 = ldg_cg_128(pB + 8);

        const __half2* pa0 = (const __half2*)&va0;
        const __half2* pa1 = (const __half2*)&va1;
        const __half2* pb0 = (const __half2*)&vb0;
        const __half2* pb1 = (const __half2*)&vb1;
        const __half2 zero2 = __float2half2_rn(0.f);

#pragma unroll
        for (int i = 0; i < 4; i++) {
            __half2 z2 = __hmax2(__hadd2(pa0[i], pb0[i]), zero2);
            float2 f = __half22float2(z2);
            acc = fmaf(f.x, w[2 * i + 0], acc);
            acc = fmaf(f.y, w[2 * i + 1], acc);
        }
#pragma unroll
        for (int i = 0; i < 4; i++) {
            __half2 z2 = __hmax2(__hadd2(pa1[i], pb1[i]), zero2);
            float2 f = __half22float2(z2);
            acc = fmaf(f.x, w[8 + 2 * i + 0], acc);
            acc = fmaf(f.y, w[8 + 2 * i + 1], acc);
        }
    }

    // reduce within each 16-lane group
#pragma unroll
    for (int off = 8; off > 0; off >>= 1)
        acc += __shfl_xor_sync(0xFFFFFFFFu, acc, off);

    if (sub == 0 && e < E) out[e] = acc + sb2;
}

// ---------------------------------------------------------------------------
extern "C" void kernel_launch(void* const* d_in, const int* in_sizes, int n_in,
                              void* d_out, int out_size)
{
    const float* h    = (const float*)d_in[0];
    const int*   src  = (const int*)d_in[1];
    const int*   dst  = (const int*)d_in[2];
    const float* W1_w = (const float*)d_in[3];
    const float* W1_b = (const float*)d_in[4];
    const float* W2_w = (const float*)d_in[5];
    const float* W2_b = (const float*)d_in[6];
    float* out = (float*)d_out;

    int n_nodes = in_sizes[0] / D_FEAT;
    int E = in_sizes[1];

    // 1) Weight reorder
    prep_w_kernel<<<(D_FEAT * NOUT + 255) / 256, 256>>>(W1_w);

    // 2) Precompute A' (with b1) and B per node — 68 KB dynamic smem
    static int smem_set = 0;
    int smem_bytes = 2 * MT * SLD * 2;   // 69632... = 2 tiles of 34816 B
    if (!smem_set) {
        cudaFuncSetAttribute(gemm_ab_kernel,
                             cudaFuncAttributeMaxDynamicSharedMemorySize,
                             smem_bytes);
        smem_set = 1;
    }
    gemm_ab_kernel<<<(n_nodes + MT - 1) / MT, 256, smem_bytes>>>(h, W1_b, n_nodes);

    // 3) Per-edge: gather, add, relu, dot
    edge_kernel<<<(E + 15) / 16, 256>>>(src, dst, W2_w, W2_b, out, E);
}